// round 2
// baseline (speedup 1.0000x reference)
#include <cuda_runtime.h>
#include <math.h>

#define HH 512
#define WW 512
#define RR 4
#define NIMG 64
#define NEL (NIMG*HH*WW)
#define TRR 64            // rows of output per strip pass
#define WPB 8             // warps per block
#define SCOLS 32          // strip width per warp
#define SBW 40            // strip row-buffer width = SCOLS + 2*RR

// Scratch (device globals: no allocation allowed in kernel_launch)
__device__ double g_partial[2048];
__device__ float  g_invSf;
__device__ float  g_A[NEL];
__device__ float  g_Bv[NEL];

// ---------------- Stage 1: deterministic global sum of |a| + 1e-12 (fp64) ----
__global__ void k_sum_partial(const float* __restrict__ a) {
    __shared__ double wsum[8];
    const int b = blockIdx.x, t = threadIdx.x;
    const float4* p = (const float4*)(a + (size_t)b * 8192);
    double acc = 0.0;
    #pragma unroll
    for (int j = 0; j < 8; j++) {
        float4 v = p[t + j * 256];
        acc += (fabs((double)v.x) + 1e-12) + (fabs((double)v.y) + 1e-12)
             + (fabs((double)v.z) + 1e-12) + (fabs((double)v.w) + 1e-12);
    }
    #pragma unroll
    for (int o = 16; o > 0; o >>= 1) acc += __shfl_down_sync(0xffffffffu, acc, o);
    if ((t & 31) == 0) wsum[t >> 5] = acc;
    __syncthreads();
    if (t == 0) {
        double s = 0.0;
        #pragma unroll
        for (int w = 0; w < 8; w++) s += wsum[w];
        g_partial[b] = s;
    }
}

__global__ void k_sum_final() {
    __shared__ double wsum[8];
    const int t = threadIdx.x;
    double acc = 0.0;
    for (int j = t; j < 2048; j += 256) acc += g_partial[j];
    #pragma unroll
    for (int o = 16; o > 0; o >>= 1) acc += __shfl_down_sync(0xffffffffu, acc, o);
    if ((t & 31) == 0) wsum[t >> 5] = acc;
    __syncthreads();
    if (t == 0) {
        double s = 0.0;
        for (int w = 0; w < 8; w++) s += wsum[w];
        g_invSf = (float)(1.0 / s);
    }
}

// ---------------- Stage 2: fused 6-quantity box filter -> A, b -----------------
// Warp-autonomous 32-col strips. Per-warp 40-wide row buffer in shared,
// __syncwarp only. Global loads for row k+1 issued before consuming row k
// (software pipeline). Vertical 9-ring in per-thread local memory (coalesced).
__global__ __launch_bounds__(WPB*32) void k_stats(
    const float* __restrict__ X, const float* __restrict__ Y,
    const float* __restrict__ Wt)
{
    __shared__ float rb[WPB][3][SBW];
    const int t = threadIdx.x;
    const int w = t >> 5, l = t & 31;
    const int img   = blockIdx.z;
    const int strip = (blockIdx.x * WPB + w) * SCOLS;
    const int br    = blockIdx.y * TRR;
    const size_t ibase = (size_t)img * (HH * WW);
    const float* __restrict__ xim = X  + ibase;
    const float* __restrict__ yim = Y  + ibase;
    const float* __restrict__ aim = Wt + ibase;
    const float invS = g_invSf;

    const int col = strip + l;
    const int ncl = min(col + RR, WW - 1) - max(col - RR, 0) + 1;

    const int c0 = strip - RR + l;          // lanes 0..31 cover cols strip-4..strip+27
    const int c1 = strip + SCOLS - RR + l;  // lanes 0..7  cover cols strip+28..strip+35
    const bool p0 = (c0 >= 0) && (c0 < WW);
    const bool p1 = (l < 2 * RR) && (c1 < WW);

    float ring[9][6];
    float acc0=0.f, acc1=0.f, acc2=0.f, acc3=0.f, acc4=0.f, acc5=0.f;
    int slot = 0;

    float xa, ya, aa, xb, yb, ab;
    // prologue load: row br-RR
    {
        const int r = br - RR;
        xa = ya = aa = xb = yb = ab = 0.f;
        if (r >= 0) {  // r < HH always here
            const size_t ro = (size_t)r * WW;
            if (p0) { xa = xim[ro+c0]; ya = yim[ro+c0]; aa = fabsf(aim[ro+c0]) + 1e-12f; }
            if (p1) { xb = xim[ro+c1]; yb = yim[ro+c1]; ab = fabsf(aim[ro+c1]) + 1e-12f; }
        }
    }

    for (int k = 0; k < TRR + 2 * RR; ++k) {
        // publish current row to warp-private buffer
        rb[w][0][l] = xa;  rb[w][1][l] = ya;  rb[w][2][l] = aa;
        if (l < 2 * RR) { rb[w][0][SCOLS+l] = xb; rb[w][1][SCOLS+l] = yb; rb[w][2][SCOLS+l] = ab; }
        __syncwarp();

        // prefetch next row while we compute (overlaps global latency)
        if (k < TRR + 2 * RR - 1) {
            const int r = br - RR + k + 1;
            xa = ya = aa = xb = yb = ab = 0.f;
            if (r >= 0 && r < HH) {
                const size_t ro = (size_t)r * WW;
                if (p0) { xa = xim[ro+c0]; ya = yim[ro+c0]; aa = fabsf(aim[ro+c0]) + 1e-12f; }
                if (p1) { xb = xim[ro+c1]; yb = yim[ro+c1]; ab = fabsf(aim[ro+c1]) + 1e-12f; }
            }
        }

        // horizontal 9-tap box of the 6 products
        float h0=0.f, h1=0.f, h2=0.f, h3=0.f, h4=0.f, h5=0.f;
        #pragma unroll
        for (int d = 0; d < 9; ++d) {
            const float xv = rb[w][0][l + d];
            const float yv = rb[w][1][l + d];
            const float av = rb[w][2][l + d];
            const float ax  = av * xv;
            const float a2x = ax * av;
            h0 += av;
            h5 += ax;
            h2 += a2x;
            h3 = fmaf(av,  yv, h3);
            h1 = fmaf(a2x, yv, h1);
            h4 = fmaf(a2x, xv, h4);
        }
        __syncwarp();  // reads done before next iteration's publish

        // vertical sliding window via per-thread local ring
        if (k >= 9) {
            acc0 -= ring[slot][0]; acc1 -= ring[slot][1]; acc2 -= ring[slot][2];
            acc3 -= ring[slot][3]; acc4 -= ring[slot][4]; acc5 -= ring[slot][5];
        }
        acc0 += h0; acc1 += h1; acc2 += h2; acc3 += h3; acc4 += h4; acc5 += h5;
        ring[slot][0] = h0; ring[slot][1] = h1; ring[slot][2] = h2;
        ring[slot][3] = h3; ring[slot][4] = h4; ring[slot][5] = h5;
        if (++slot == 9) slot = 0;

        if (k >= 2 * RR) {
            const int ro = br + k - 2 * RR;
            const int nr = min(ro + RR, HH - 1) - max(ro - RR, 0) + 1;
            const float Nf  = (float)(nr * ncl);
            const float num = fmaf(-(acc2 * acc3), invS, acc1);
            const float den = fabsf(fmaf(-(acc2 * acc5), invS, acc4)) + Nf * 1e-8f;
            const float Av  = __fdividef(num, den);
            const float bv  = __fdividef(fmaf(-Av, acc5, acc3), acc0);
            const size_t o  = ibase + (size_t)ro * WW + col;
            g_A[o]  = Av;
            g_Bv[o] = bv;
        }
    }
}

// ---------------- Stage 3: box filter A,b + final blend ------------------------
__global__ __launch_bounds__(WPB*32) void k_final(
    const float* __restrict__ X, float* __restrict__ out)
{
    __shared__ float rb[WPB][2][SBW];
    const int t = threadIdx.x;
    const int w = t >> 5, l = t & 31;
    const int img   = blockIdx.z;
    const int strip = (blockIdx.x * WPB + w) * SCOLS;
    const int br    = blockIdx.y * TRR;
    const size_t ibase = (size_t)img * (HH * WW);
    const float* __restrict__ Aim = g_A  + ibase;
    const float* __restrict__ Bim = g_Bv + ibase;

    const int col = strip + l;
    const int ncl = min(col + RR, WW - 1) - max(col - RR, 0) + 1;

    const int c0 = strip - RR + l;
    const int c1 = strip + SCOLS - RR + l;
    const bool p0 = (c0 >= 0) && (c0 < WW);
    const bool p1 = (l < 2 * RR) && (c1 < WW);

    float ring[9][2];
    float accA = 0.f, accB = 0.f;
    int slot = 0;

    float va, vb, ua, ub;
    {
        const int r = br - RR;
        va = vb = ua = ub = 0.f;
        if (r >= 0) {
            const size_t ro = (size_t)r * WW;
            if (p0) { va = Aim[ro+c0]; ua = Bim[ro+c0]; }
            if (p1) { vb = Aim[ro+c1]; ub = Bim[ro+c1]; }
        }
    }

    for (int k = 0; k < TRR + 2 * RR; ++k) {
        rb[w][0][l] = va;  rb[w][1][l] = ua;
        if (l < 2 * RR) { rb[w][0][SCOLS+l] = vb; rb[w][1][SCOLS+l] = ub; }
        __syncwarp();

        if (k < TRR + 2 * RR - 1) {
            const int r = br - RR + k + 1;
            va = vb = ua = ub = 0.f;
            if (r >= 0 && r < HH) {
                const size_t ro = (size_t)r * WW;
                if (p0) { va = Aim[ro+c0]; ua = Bim[ro+c0]; }
                if (p1) { vb = Aim[ro+c1]; ub = Bim[ro+c1]; }
            }
        }

        float hA = 0.f, hB = 0.f;
        #pragma unroll
        for (int d = 0; d < 9; ++d) {
            hA += rb[w][0][l + d];
            hB += rb[w][1][l + d];
        }
        __syncwarp();

        if (k >= 9) { accA -= ring[slot][0]; accB -= ring[slot][1]; }
        accA += hA; accB += hB;
        ring[slot][0] = hA; ring[slot][1] = hB;
        if (++slot == 9) slot = 0;

        if (k >= 2 * RR) {
            const int ro = br + k - 2 * RR;
            const int nr = min(ro + RR, HH - 1) - max(ro - RR, 0) + 1;
            const float rcpN = __fdividef(1.f, (float)(nr * ncl));
            const size_t o = ibase + (size_t)ro * WW + col;
            const float xv = X[o];
            out[o] = (accA * xv + accB) * rcpN;
        }
    }
}

extern "C" void kernel_launch(void* const* d_in, const int* in_sizes, int n_in,
                              void* d_out, int out_size) {
    const float* x = (const float*)d_in[0];  // lr_x
    const float* y = (const float*)d_in[1];  // lr_y
    const float* a = (const float*)d_in[2];  // l_a
    float* out = (float*)d_out;

    k_sum_partial<<<2048, 256>>>(a);
    k_sum_final<<<1, 256>>>();

    dim3 grid(WW / (WPB * SCOLS), HH / TRR, NIMG);
    k_stats<<<grid, WPB * 32>>>(x, y, a);
    k_final<<<grid, WPB * 32>>>(x, out);
}

// round 3
// speedup vs baseline: 2.6420x; 2.6420x over previous
#include <cuda_runtime.h>
#include <math.h>

#define HH 512
#define WW 512
#define RR 4
#define NIMG 64
#define NEL (NIMG*HH*WW)

// tile geometry (both stencil kernels)
#define TC 32            // output cols per block
#define TR 56            // output rows per block
#define HR 64            // halo rows = TR + 2*RR
#define HC 40            // halo cols = TC + 2*RR
#define PIN 41           // input tile pitch (floats)  -> conflict-free column reads
#define PH  33           // h tile pitch (floats)      -> conflict-free both ways
#define NTHR 256

// Scratch (device globals: no allocation allowed)
__device__ double g_partial[2048];
__device__ float  g_invSf;
__device__ float  g_A[NEL];
__device__ float  g_Bv[NEL];

// ---------------- Stage 1: deterministic global sum of |a| + 1e-12 (fp64) ----
__global__ void k_sum_partial(const float* __restrict__ a) {
    __shared__ double wsum[8];
    const int b = blockIdx.x, t = threadIdx.x;
    const float4* p = (const float4*)(a + (size_t)b * 8192);
    double acc = 0.0;
    #pragma unroll
    for (int j = 0; j < 8; j++) {
        float4 v = p[t + j * 256];
        acc += (fabs((double)v.x) + 1e-12) + (fabs((double)v.y) + 1e-12)
             + (fabs((double)v.z) + 1e-12) + (fabs((double)v.w) + 1e-12);
    }
    #pragma unroll
    for (int o = 16; o > 0; o >>= 1) acc += __shfl_down_sync(0xffffffffu, acc, o);
    if ((t & 31) == 0) wsum[t >> 5] = acc;
    __syncthreads();
    if (t == 0) {
        double s = 0.0;
        #pragma unroll
        for (int w = 0; w < 8; w++) s += wsum[w];
        g_partial[b] = s;
    }
}

__global__ void k_sum_final() {
    __shared__ double wsum[8];
    const int t = threadIdx.x;
    double acc = 0.0;
    for (int j = t; j < 2048; j += 256) acc += g_partial[j];
    #pragma unroll
    for (int o = 16; o > 0; o >>= 1) acc += __shfl_down_sync(0xffffffffu, acc, o);
    if ((t & 31) == 0) wsum[t >> 5] = acc;
    __syncthreads();
    if (t == 0) {
        double s = 0.0;
        for (int w = 0; w < 8; w++) s += wsum[w];
        g_invSf = (float)(1.0 / s);
    }
}

// ---------------- Stage 2: fused 6-quantity box filter -> A, b -----------------
// Fully parallel tile: Phase A load halo -> shared; Phase B horizontal 9-tap
// (in-register sliding, 8 cols/thread) -> shared; Phase C vertical 9-tap
// (in-register sliding, 7 rows/thread) + solve. Two barriers total.
__global__ __launch_bounds__(NTHR) void k_stats(
    const float* __restrict__ X, const float* __restrict__ Y,
    const float* __restrict__ Wt)
{
    extern __shared__ float smem[];
    float* sX = smem;                 // [HR][PIN]
    float* sY = sX + HR * PIN;
    float* sA = sY + HR * PIN;
    float* sH = sA + HR * PIN;        // [6][HR][PH]

    const int tid = threadIdx.x;
    const int img = blockIdx.z;
    const int bc  = blockIdx.x * TC;
    const int br  = blockIdx.y * TR;
    const size_t ibase = (size_t)img * (HH * WW);

    // ---- Phase A: halo load (zero outside image = truncated box) ----
    #pragma unroll
    for (int it = 0; it < (HR * HC + NTHR - 1) / NTHR; ++it) {
        int idx = tid + it * NTHR;
        if (idx < HR * HC) {
            int rh = idx / HC, c = idx % HC;
            int gr = br - RR + rh, gc = bc - RR + c;
            float xv = 0.f, yv = 0.f, av = 0.f;
            if (gr >= 0 && gr < HH && gc >= 0 && gc < WW) {
                size_t o = ibase + (size_t)gr * WW + gc;
                xv = X[o]; yv = Y[o]; av = fabsf(Wt[o]) + 1e-12f;
            }
            sX[rh * PIN + c] = xv;
            sY[rh * PIN + c] = yv;
            sA[rh * PIN + c] = av;
        }
    }
    __syncthreads();

    // ---- Phase B: horizontal 9-tap, sliding over 8 cols per thread ----
    {
        const int cg = tid >> 6;          // 0..3 (8-col group)
        const int rh = tid & 63;          // 0..63 halo row
        const int base = rh * PIN + cg * 8;
        const int hb   = rh * PH  + cg * 8;

        float h0=0.f,h1=0.f,h2=0.f,h3=0.f,h4=0.f,h5=0.f;
        #pragma unroll
        for (int d = 0; d < 9; ++d) {
            const float xv = sX[base + d], yv = sY[base + d], av = sA[base + d];
            const float ax = av * xv, a2x = ax * av;
            h0 += av; h5 += ax; h2 += a2x;
            h3 = fmaf(av,  yv, h3);
            h1 = fmaf(a2x, yv, h1);
            h4 = fmaf(a2x, xv, h4);
        }
        sH[0*HR*PH + hb] = h0; sH[1*HR*PH + hb] = h1; sH[2*HR*PH + hb] = h2;
        sH[3*HR*PH + hb] = h3; sH[4*HR*PH + hb] = h4; sH[5*HR*PH + hb] = h5;

        #pragma unroll
        for (int s = 1; s < 8; ++s) {
            float xv = sX[base + 8 + s], yv = sY[base + 8 + s], av = sA[base + 8 + s];
            float ax = av * xv, a2x = ax * av;
            h0 += av; h5 += ax; h2 += a2x;
            h3 = fmaf(av,  yv, h3);
            h1 = fmaf(a2x, yv, h1);
            h4 = fmaf(a2x, xv, h4);
            xv = sX[base + s - 1]; yv = sY[base + s - 1]; av = sA[base + s - 1];
            ax = av * xv; a2x = ax * av;
            h0 -= av; h5 -= ax; h2 -= a2x;
            h3 = fmaf(-av,  yv, h3);
            h1 = fmaf(-a2x, yv, h1);
            h4 = fmaf(-a2x, xv, h4);
            sH[0*HR*PH + hb + s] = h0; sH[1*HR*PH + hb + s] = h1;
            sH[2*HR*PH + hb + s] = h2; sH[3*HR*PH + hb + s] = h3;
            sH[4*HR*PH + hb + s] = h4; sH[5*HR*PH + hb + s] = h5;
        }
    }
    __syncthreads();

    // ---- Phase C: vertical 9-tap sliding over 7 rows per thread + solve ----
    {
        const int c   = tid & 31;
        const int seg = tid >> 5;         // 0..7 -> rows seg*7 .. seg*7+6
        const int col = bc + c;
        const int ncl = min(col + RR, WW - 1) - max(col - RR, 0) + 1;
        const float invS = g_invSf;
        const int r0 = seg * 7;

        float a0=0.f,a1=0.f,a2=0.f,a3=0.f,a4=0.f,a5=0.f;
        #pragma unroll
        for (int d = 0; d < 9; ++d) {
            const int hb = (r0 + d) * PH + c;
            a0 += sH[0*HR*PH + hb]; a1 += sH[1*HR*PH + hb];
            a2 += sH[2*HR*PH + hb]; a3 += sH[3*HR*PH + hb];
            a4 += sH[4*HR*PH + hb]; a5 += sH[5*HR*PH + hb];
        }
        #pragma unroll
        for (int i = 0; i < 7; ++i) {
            const int gro = br + r0 + i;
            if (gro < HH) {
                const int nr = min(gro + RR, HH - 1) - max(gro - RR, 0) + 1;
                const float Nf  = (float)(nr * ncl);
                const float num = fmaf(-(a2 * a3), invS, a1);
                const float den = fabsf(fmaf(-(a2 * a5), invS, a4)) + Nf * 1e-8f;
                const float Av  = __fdividef(num, den);
                const float bv  = __fdividef(fmaf(-Av, a5, a3), a0);
                const size_t o  = ibase + (size_t)gro * WW + col;
                g_A[o]  = Av;
                g_Bv[o] = bv;
            }
            if (i < 6) {
                const int ha = (r0 + 9 + i) * PH + c;
                const int hs = (r0 + i) * PH + c;
                a0 += sH[0*HR*PH + ha] - sH[0*HR*PH + hs];
                a1 += sH[1*HR*PH + ha] - sH[1*HR*PH + hs];
                a2 += sH[2*HR*PH + ha] - sH[2*HR*PH + hs];
                a3 += sH[3*HR*PH + ha] - sH[3*HR*PH + hs];
                a4 += sH[4*HR*PH + ha] - sH[4*HR*PH + hs];
                a5 += sH[5*HR*PH + ha] - sH[5*HR*PH + hs];
            }
        }
    }
}

// ---------------- Stage 3: box filter A,b + final blend ------------------------
__global__ __launch_bounds__(NTHR) void k_final(
    const float* __restrict__ X, float* __restrict__ out)
{
    __shared__ float sAv[HR * PIN];
    __shared__ float sBv[HR * PIN];
    __shared__ float sHA[HR * PH];
    __shared__ float sHB[HR * PH];

    const int tid = threadIdx.x;
    const int img = blockIdx.z;
    const int bc  = blockIdx.x * TC;
    const int br  = blockIdx.y * TR;
    const size_t ibase = (size_t)img * (HH * WW);

    // Phase A
    #pragma unroll
    for (int it = 0; it < (HR * HC + NTHR - 1) / NTHR; ++it) {
        int idx = tid + it * NTHR;
        if (idx < HR * HC) {
            int rh = idx / HC, c = idx % HC;
            int gr = br - RR + rh, gc = bc - RR + c;
            float av = 0.f, bv = 0.f;
            if (gr >= 0 && gr < HH && gc >= 0 && gc < WW) {
                size_t o = ibase + (size_t)gr * WW + gc;
                av = g_A[o]; bv = g_Bv[o];
            }
            sAv[rh * PIN + c] = av;
            sBv[rh * PIN + c] = bv;
        }
    }
    __syncthreads();

    // Phase B: horizontal 9-tap, sliding
    {
        const int cg = tid >> 6;
        const int rh = tid & 63;
        const int base = rh * PIN + cg * 8;
        const int hb   = rh * PH  + cg * 8;
        float hA = 0.f, hB = 0.f;
        #pragma unroll
        for (int d = 0; d < 9; ++d) { hA += sAv[base + d]; hB += sBv[base + d]; }
        sHA[hb] = hA; sHB[hb] = hB;
        #pragma unroll
        for (int s = 1; s < 8; ++s) {
            hA += sAv[base + 8 + s] - sAv[base + s - 1];
            hB += sBv[base + 8 + s] - sBv[base + s - 1];
            sHA[hb + s] = hA; sHB[hb + s] = hB;
        }
    }
    __syncthreads();

    // Phase C: vertical 9-tap sliding + blend
    {
        const int c   = tid & 31;
        const int seg = tid >> 5;
        const int col = bc + c;
        const int ncl = min(col + RR, WW - 1) - max(col - RR, 0) + 1;
        const int r0 = seg * 7;

        float aA = 0.f, aB = 0.f;
        #pragma unroll
        for (int d = 0; d < 9; ++d) {
            const int hb = (r0 + d) * PH + c;
            aA += sHA[hb]; aB += sHB[hb];
        }
        #pragma unroll
        for (int i = 0; i < 7; ++i) {
            const int gro = br + r0 + i;
            if (gro < HH) {
                const int nr = min(gro + RR, HH - 1) - max(gro - RR, 0) + 1;
                const float rcpN = __fdividef(1.f, (float)(nr * ncl));
                const size_t o = ibase + (size_t)gro * WW + col;
                const float xv = X[o];
                out[o] = (aA * xv + aB) * rcpN;
            }
            if (i < 6) {
                const int ha = (r0 + 9 + i) * PH + c;
                const int hs = (r0 + i) * PH + c;
                aA += sHA[ha] - sHA[hs];
                aB += sHB[ha] - sHB[hs];
            }
        }
    }
}

extern "C" void kernel_launch(void* const* d_in, const int* in_sizes, int n_in,
                              void* d_out, int out_size) {
    const float* x = (const float*)d_in[0];  // lr_x
    const float* y = (const float*)d_in[1];  // lr_y
    const float* a = (const float*)d_in[2];  // l_a
    float* out = (float*)d_out;

    k_sum_partial<<<2048, 256>>>(a);
    k_sum_final<<<1, 256>>>();

    const int smem_stats = (3 * HR * PIN + 6 * HR * PH) * (int)sizeof(float); // 82176 B
    cudaFuncSetAttribute(k_stats, cudaFuncAttributeMaxDynamicSharedMemorySize, smem_stats);

    dim3 grid(WW / TC, (HH + TR - 1) / TR, NIMG);  // 16 x 10 x 64
    k_stats<<<grid, NTHR, smem_stats>>>(x, y, a);
    k_final<<<grid, NTHR>>>(x, out);
}

// round 4
// speedup vs baseline: 3.5583x; 1.3468x over previous
#include <cuda_runtime.h>
#include <math.h>

#define HH 512
#define WW 512
#define RR 4
#define NIMG 64
#define NEL (NIMG*HH*WW)

// tile geometry (both stencil kernels)
#define TC 32            // output cols per block
#define TR 24            // output rows per block
#define HR 32            // halo rows = TR + 2*RR
#define HC 40            // halo cols = TC + 2*RR
#define PIN 41           // input tile pitch (floats)  -> conflict-free everywhere
#define PH  33           // h tile pitch (floats)      -> conflict-free everywhere
#define NTHR 256
#define GY ((HH + TR - 1) / TR)   // 22

// Scratch (device globals: no allocation allowed)
__device__ double g_partial[2048];
__device__ float  g_invSf;
__device__ float  g_A[NEL];
__device__ float  g_Bv[NEL];

// ---------------- Stage 1: deterministic global sum of |a| + 1e-12 (fp64) ----
__global__ void k_sum_partial(const float* __restrict__ a) {
    __shared__ double wsum[8];
    const int b = blockIdx.x, t = threadIdx.x;
    const float4* p = (const float4*)(a + (size_t)b * 8192);
    double acc = 0.0;
    #pragma unroll
    for (int j = 0; j < 8; j++) {
        float4 v = p[t + j * 256];
        acc += (fabs((double)v.x) + 1e-12) + (fabs((double)v.y) + 1e-12)
             + (fabs((double)v.z) + 1e-12) + (fabs((double)v.w) + 1e-12);
    }
    #pragma unroll
    for (int o = 16; o > 0; o >>= 1) acc += __shfl_down_sync(0xffffffffu, acc, o);
    if ((t & 31) == 0) wsum[t >> 5] = acc;
    __syncthreads();
    if (t == 0) {
        double s = 0.0;
        #pragma unroll
        for (int w = 0; w < 8; w++) s += wsum[w];
        g_partial[b] = s;
    }
}

__global__ void k_sum_final() {
    __shared__ double wsum[8];
    const int t = threadIdx.x;
    double acc = 0.0;
    for (int j = t; j < 2048; j += 256) acc += g_partial[j];
    #pragma unroll
    for (int o = 16; o > 0; o >>= 1) acc += __shfl_down_sync(0xffffffffu, acc, o);
    if ((t & 31) == 0) wsum[t >> 5] = acc;
    __syncthreads();
    if (t == 0) {
        double s = 0.0;
        for (int w = 0; w < 8; w++) s += wsum[w];
        g_invSf = (float)(1.0 / s);
    }
}

// ---------------- Stage 2: fused 6-quantity box filter -> A, b -----------------
// Small tile (32x24 out, 40x32 halo) for 5 blocks/SM. Phase A: float4 halo load
// (each aligned group fully in or fully out of image). Phase B: horizontal 9-tap
// in-register sliding, 4 cols/thread. Phase C: vertical 9-tap sliding, 3 rows/
// thread, + solve. Two barriers.
__global__ __launch_bounds__(NTHR) void k_stats(
    const float* __restrict__ X, const float* __restrict__ Y,
    const float* __restrict__ Wt)
{
    __shared__ float sX[HR * PIN];
    __shared__ float sY[HR * PIN];
    __shared__ float sA[HR * PIN];
    __shared__ float sH[6][HR * PH];

    const int tid = threadIdx.x;
    const int img = blockIdx.z;
    const int bc  = blockIdx.x * TC;
    const int br  = blockIdx.y * TR;
    const size_t ibase = (size_t)img * (HH * WW);

    // ---- Phase A: vectorized halo load (zero outside = truncated box) ----
    #pragma unroll
    for (int it = 0; it < 2; ++it) {
        const int idx = tid + it * NTHR;
        if (idx < HR * (HC / 4)) {                 // 320 items
            const int rh = idx / (HC / 4);
            const int vq = idx % (HC / 4);
            const int gr = br - RR + rh;
            const int gc = bc - RR + vq * 4;       // multiple of 4, aligned
            float4 xv = make_float4(0.f,0.f,0.f,0.f);
            float4 yv = xv, av = xv;
            if (gr >= 0 && gr < HH && gc >= 0 && gc < WW) {
                const size_t o = ibase + (size_t)gr * WW + gc;
                xv = *(const float4*)(X  + o);
                yv = *(const float4*)(Y  + o);
                av = *(const float4*)(Wt + o);
            }
            const int sb = rh * PIN + vq * 4;
            sX[sb+0]=xv.x; sX[sb+1]=xv.y; sX[sb+2]=xv.z; sX[sb+3]=xv.w;
            sY[sb+0]=yv.x; sY[sb+1]=yv.y; sY[sb+2]=yv.z; sY[sb+3]=yv.w;
            sA[sb+0]=fabsf(av.x)+1e-12f; sA[sb+1]=fabsf(av.y)+1e-12f;
            sA[sb+2]=fabsf(av.z)+1e-12f; sA[sb+3]=fabsf(av.w)+1e-12f;
        }
    }
    __syncthreads();

    // ---- Phase B: horizontal 9-tap, sliding over 4 cols per thread ----
    {
        const int rh = tid & (HR - 1);       // 0..31 (lanes of a warp -> rows)
        const int cg = tid >> 5;             // 0..7  (warp -> 4-col group)
        const int base = rh * PIN + cg * 4;
        const int hb   = rh * PH  + cg * 4;

        float h0=0.f,h1=0.f,h2=0.f,h3=0.f,h4=0.f,h5=0.f;
        #pragma unroll
        for (int d = 0; d < 9; ++d) {
            const float xv = sX[base + d], yv = sY[base + d], av = sA[base + d];
            const float ax = av * xv, a2x = ax * av;
            h0 += av; h5 += ax; h2 += a2x;
            h3 = fmaf(av,  yv, h3);
            h1 = fmaf(a2x, yv, h1);
            h4 = fmaf(a2x, xv, h4);
        }
        sH[0][hb]=h0; sH[1][hb]=h1; sH[2][hb]=h2;
        sH[3][hb]=h3; sH[4][hb]=h4; sH[5][hb]=h5;

        #pragma unroll
        for (int s = 1; s < 4; ++s) {
            float xv = sX[base + 8 + s], yv = sY[base + 8 + s], av = sA[base + 8 + s];
            float ax = av * xv, a2x = ax * av;
            h0 += av; h5 += ax; h2 += a2x;
            h3 = fmaf(av,  yv, h3);
            h1 = fmaf(a2x, yv, h1);
            h4 = fmaf(a2x, xv, h4);
            xv = sX[base + s - 1]; yv = sY[base + s - 1]; av = sA[base + s - 1];
            ax = av * xv; a2x = ax * av;
            h0 -= av; h5 -= ax; h2 -= a2x;
            h3 = fmaf(-av,  yv, h3);
            h1 = fmaf(-a2x, yv, h1);
            h4 = fmaf(-a2x, xv, h4);
            sH[0][hb+s]=h0; sH[1][hb+s]=h1; sH[2][hb+s]=h2;
            sH[3][hb+s]=h3; sH[4][hb+s]=h4; sH[5][hb+s]=h5;
        }
    }
    __syncthreads();

    // ---- Phase C: vertical 9-tap sliding over 3 rows per thread + solve ----
    {
        const int c   = tid & 31;
        const int seg = tid >> 5;            // 0..7 -> rows seg*3 .. seg*3+2
        const int col = bc + c;
        const int ncl = min(col + RR, WW - 1) - max(col - RR, 0) + 1;
        const float invS = g_invSf;
        const int r0 = seg * 3;

        float a0=0.f,a1=0.f,a2=0.f,a3=0.f,a4=0.f,a5=0.f;
        #pragma unroll
        for (int d = 0; d < 9; ++d) {
            const int hb = (r0 + d) * PH + c;
            a0 += sH[0][hb]; a1 += sH[1][hb]; a2 += sH[2][hb];
            a3 += sH[3][hb]; a4 += sH[4][hb]; a5 += sH[5][hb];
        }
        #pragma unroll
        for (int i = 0; i < 3; ++i) {
            const int gro = br + r0 + i;
            if (gro < HH) {
                const int nr = min(gro + RR, HH - 1) - max(gro - RR, 0) + 1;
                const float Nf  = (float)(nr * ncl);
                const float num = fmaf(-(a2 * a3), invS, a1);
                const float den = fabsf(fmaf(-(a2 * a5), invS, a4)) + Nf * 1e-8f;
                const float Av  = __fdividef(num, den);
                const float bv  = __fdividef(fmaf(-Av, a5, a3), a0);
                const size_t o  = ibase + (size_t)gro * WW + col;
                g_A[o]  = Av;
                g_Bv[o] = bv;
            }
            if (i < 2) {
                const int ha = (r0 + 9 + i) * PH + c;
                const int hs = (r0 + i) * PH + c;
                a0 += sH[0][ha] - sH[0][hs];
                a1 += sH[1][ha] - sH[1][hs];
                a2 += sH[2][ha] - sH[2][hs];
                a3 += sH[3][ha] - sH[3][hs];
                a4 += sH[4][ha] - sH[4][hs];
                a5 += sH[5][ha] - sH[5][hs];
            }
        }
    }
}

// ---------------- Stage 3: box filter A,b + final blend ------------------------
__global__ __launch_bounds__(NTHR) void k_final(
    const float* __restrict__ X, float* __restrict__ out)
{
    __shared__ float sAv[HR * PIN];
    __shared__ float sBv[HR * PIN];
    __shared__ float sHA[HR * PH];
    __shared__ float sHB[HR * PH];

    const int tid = threadIdx.x;
    const int img = blockIdx.z;
    const int bc  = blockIdx.x * TC;
    const int br  = blockIdx.y * TR;
    const size_t ibase = (size_t)img * (HH * WW);

    // Phase A: vectorized halo load of A, b
    #pragma unroll
    for (int it = 0; it < 2; ++it) {
        const int idx = tid + it * NTHR;
        if (idx < HR * (HC / 4)) {
            const int rh = idx / (HC / 4);
            const int vq = idx % (HC / 4);
            const int gr = br - RR + rh;
            const int gc = bc - RR + vq * 4;
            float4 av = make_float4(0.f,0.f,0.f,0.f);
            float4 bv = av;
            if (gr >= 0 && gr < HH && gc >= 0 && gc < WW) {
                const size_t o = ibase + (size_t)gr * WW + gc;
                av = *(const float4*)(g_A  + o);
                bv = *(const float4*)(g_Bv + o);
            }
            const int sb = rh * PIN + vq * 4;
            sAv[sb+0]=av.x; sAv[sb+1]=av.y; sAv[sb+2]=av.z; sAv[sb+3]=av.w;
            sBv[sb+0]=bv.x; sBv[sb+1]=bv.y; sBv[sb+2]=bv.z; sBv[sb+3]=bv.w;
        }
    }
    __syncthreads();

    // Phase B: horizontal 9-tap, sliding over 4 cols per thread
    {
        const int rh = tid & (HR - 1);
        const int cg = tid >> 5;
        const int base = rh * PIN + cg * 4;
        const int hb   = rh * PH  + cg * 4;
        float hA = 0.f, hB = 0.f;
        #pragma unroll
        for (int d = 0; d < 9; ++d) { hA += sAv[base + d]; hB += sBv[base + d]; }
        sHA[hb] = hA; sHB[hb] = hB;
        #pragma unroll
        for (int s = 1; s < 4; ++s) {
            hA += sAv[base + 8 + s] - sAv[base + s - 1];
            hB += sBv[base + 8 + s] - sBv[base + s - 1];
            sHA[hb + s] = hA; sHB[hb + s] = hB;
        }
    }
    __syncthreads();

    // Phase C: vertical 9-tap sliding + blend
    {
        const int c   = tid & 31;
        const int seg = tid >> 5;
        const int col = bc + c;
        const int ncl = min(col + RR, WW - 1) - max(col - RR, 0) + 1;
        const int r0 = seg * 3;

        float aA = 0.f, aB = 0.f;
        #pragma unroll
        for (int d = 0; d < 9; ++d) {
            const int hb = (r0 + d) * PH + c;
            aA += sHA[hb]; aB += sHB[hb];
        }
        #pragma unroll
        for (int i = 0; i < 3; ++i) {
            const int gro = br + r0 + i;
            if (gro < HH) {
                const int nr = min(gro + RR, HH - 1) - max(gro - RR, 0) + 1;
                const float rcpN = __fdividef(1.f, (float)(nr * ncl));
                const size_t o = ibase + (size_t)gro * WW + col;
                const float xv = X[o];
                out[o] = (aA * xv + aB) * rcpN;
            }
            if (i < 2) {
                const int ha = (r0 + 9 + i) * PH + c;
                const int hs = (r0 + i) * PH + c;
                aA += sHA[ha] - sHA[hs];
                aB += sHB[ha] - sHB[hs];
            }
        }
    }
}

extern "C" void kernel_launch(void* const* d_in, const int* in_sizes, int n_in,
                              void* d_out, int out_size) {
    const float* x = (const float*)d_in[0];  // lr_x
    const float* y = (const float*)d_in[1];  // lr_y
    const float* a = (const float*)d_in[2];  // l_a
    float* out = (float*)d_out;

    k_sum_partial<<<2048, 256>>>(a);
    k_sum_final<<<1, 256>>>();

    dim3 grid(WW / TC, GY, NIMG);  // 16 x 22 x 64
    k_stats<<<grid, NTHR>>>(x, y, a);
    k_final<<<grid, NTHR>>>(x, out);
}

// round 5
// speedup vs baseline: 3.5656x; 1.0021x over previous
#include <cuda_runtime.h>
#include <math.h>

#define HH 512
#define WW 512
#define RR 4
#define NIMG 64
#define NEL (NIMG*HH*WW)

// tile geometry (both stencil kernels)
#define TC 32            // output cols per block
#define TR 24            // output rows per block
#define HR 32            // halo rows = TR + 2*RR
#define HC 40            // halo cols = TC + 2*RR
#define PIN 41           // scalar plane pitch (floats)   -> conflict-free
#define PIN2 41          // float2 plane pitch (float2s)  -> conflict-free
#define PH2 33           // h plane pitch (float2s)       -> conflict-free
#define NTHR 256
#define GY ((HH + TR - 1) / TR)   // 22

// Scratch (device globals: no allocation allowed)
__device__ double g_partial[2048];
__device__ float  g_invSf;
__device__ float2 g_AB[NEL];     // interleaved (A, b)

// ---------------- Stage 1: deterministic global sum of |a| + 1e-12 (fp64) ----
__global__ void k_sum_partial(const float* __restrict__ a) {
    __shared__ double wsum[8];
    const int b = blockIdx.x, t = threadIdx.x;
    const float4* p = (const float4*)(a + (size_t)b * 8192);
    double acc = 0.0;
    #pragma unroll
    for (int j = 0; j < 8; j++) {
        float4 v = p[t + j * 256];
        acc += (fabs((double)v.x) + 1e-12) + (fabs((double)v.y) + 1e-12)
             + (fabs((double)v.z) + 1e-12) + (fabs((double)v.w) + 1e-12);
    }
    #pragma unroll
    for (int o = 16; o > 0; o >>= 1) acc += __shfl_down_sync(0xffffffffu, acc, o);
    if ((t & 31) == 0) wsum[t >> 5] = acc;
    __syncthreads();
    if (t == 0) {
        double s = 0.0;
        #pragma unroll
        for (int w = 0; w < 8; w++) s += wsum[w];
        g_partial[b] = s;
    }
}

__global__ void k_sum_final() {
    __shared__ double wsum[8];
    const int t = threadIdx.x;
    double acc = 0.0;
    for (int j = t; j < 2048; j += 256) acc += g_partial[j];
    #pragma unroll
    for (int o = 16; o > 0; o >>= 1) acc += __shfl_down_sync(0xffffffffu, acc, o);
    if ((t & 31) == 0) wsum[t >> 5] = acc;
    __syncthreads();
    if (t == 0) {
        double s = 0.0;
        for (int w = 0; w < 8; w++) s += wsum[w];
        g_invSf = (float)(1.0 / s);
    }
}

// ---------------- Stage 2: fused 6-quantity box filter -> (A,b) ----------------
__global__ __launch_bounds__(NTHR) void k_stats(
    const float* __restrict__ X, const float* __restrict__ Y,
    const float* __restrict__ Wt)
{
    __shared__ float2 sXY[HR * PIN2];       // packed (x, y)
    __shared__ float  sA [HR * PIN];        // |a| + eps
    __shared__ float2 sH0[HR * PH2];        // (h_a,    h_a2xy)
    __shared__ float2 sH1[HR * PH2];        // (h_a2x,  h_ay)
    __shared__ float2 sH2[HR * PH2];        // (h_a2x2, h_ax)

    const int tid = threadIdx.x;
    const int img = blockIdx.z;
    const int bc  = blockIdx.x * TC;
    const int br  = blockIdx.y * TR;
    const size_t ibase = (size_t)img * (HH * WW);

    // ---- Phase A: vectorized halo load (zero outside = truncated box) ----
    #pragma unroll
    for (int it = 0; it < 2; ++it) {
        const int idx = tid + it * NTHR;
        if (idx < HR * (HC / 4)) {                 // 320 items
            const int rh = idx / (HC / 4);
            const int vq = idx % (HC / 4);
            const int gr = br - RR + rh;
            const int gc = bc - RR + vq * 4;       // multiple of 4, aligned
            float4 xv = make_float4(0.f,0.f,0.f,0.f);
            float4 yv = xv, av = xv;
            if (gr >= 0 && gr < HH && gc >= 0 && gc < WW) {
                const size_t o = ibase + (size_t)gr * WW + gc;
                xv = *(const float4*)(X  + o);
                yv = *(const float4*)(Y  + o);
                av = *(const float4*)(Wt + o);
            }
            const int sb2 = rh * PIN2 + vq * 4;
            sXY[sb2+0] = make_float2(xv.x, yv.x);
            sXY[sb2+1] = make_float2(xv.y, yv.y);
            sXY[sb2+2] = make_float2(xv.z, yv.z);
            sXY[sb2+3] = make_float2(xv.w, yv.w);
            const int sb = rh * PIN + vq * 4;
            sA[sb+0]=fabsf(av.x)+1e-12f; sA[sb+1]=fabsf(av.y)+1e-12f;
            sA[sb+2]=fabsf(av.z)+1e-12f; sA[sb+3]=fabsf(av.w)+1e-12f;
        }
    }
    __syncthreads();

    // ---- Phase B: horizontal 9-tap, sliding over 4 cols per thread ----
    {
        const int rh = tid & (HR - 1);       // 0..31
        const int cg = tid >> 5;             // 0..7
        const int b2  = rh * PIN2 + cg * 4;
        const int bA  = rh * PIN  + cg * 4;
        const int hb  = rh * PH2  + cg * 4;

        float h0=0.f,h1=0.f,h2=0.f,h3=0.f,h4=0.f,h5=0.f;
        #pragma unroll
        for (int d = 0; d < 9; ++d) {
            const float2 xy = sXY[b2 + d];
            const float  av = sA [bA + d];
            const float ax = av * xy.x, a2x = ax * av;
            h0 += av; h5 += ax; h2 += a2x;
            h3 = fmaf(av,  xy.y, h3);
            h1 = fmaf(a2x, xy.y, h1);
            h4 = fmaf(a2x, xy.x, h4);
        }
        sH0[hb] = make_float2(h0, h1);
        sH1[hb] = make_float2(h2, h3);
        sH2[hb] = make_float2(h4, h5);

        #pragma unroll
        for (int s = 1; s < 4; ++s) {
            float2 xy = sXY[b2 + 8 + s];
            float  av = sA [bA + 8 + s];
            float ax = av * xy.x, a2x = ax * av;
            h0 += av; h5 += ax; h2 += a2x;
            h3 = fmaf(av,  xy.y, h3);
            h1 = fmaf(a2x, xy.y, h1);
            h4 = fmaf(a2x, xy.x, h4);
            xy = sXY[b2 + s - 1];
            av = sA [bA + s - 1];
            ax = av * xy.x; a2x = ax * av;
            h0 -= av; h5 -= ax; h2 -= a2x;
            h3 = fmaf(-av,  xy.y, h3);
            h1 = fmaf(-a2x, xy.y, h1);
            h4 = fmaf(-a2x, xy.x, h4);
            sH0[hb+s] = make_float2(h0, h1);
            sH1[hb+s] = make_float2(h2, h3);
            sH2[hb+s] = make_float2(h4, h5);
        }
    }
    __syncthreads();

    // ---- Phase C: vertical 9-tap sliding over 3 rows per thread + solve ----
    {
        const int c   = tid & 31;
        const int seg = tid >> 5;            // 0..7 -> rows seg*3 ..
        const int col = bc + c;
        const int ncl = min(col + RR, WW - 1) - max(col - RR, 0) + 1;
        const float invS = g_invSf;
        const int r0 = seg * 3;

        float a0=0.f,a1=0.f,a2=0.f,a3=0.f,a4=0.f,a5=0.f;
        #pragma unroll
        for (int d = 0; d < 9; ++d) {
            const int hb = (r0 + d) * PH2 + c;
            const float2 p = sH0[hb], q = sH1[hb], r = sH2[hb];
            a0 += p.x; a1 += p.y; a2 += q.x;
            a3 += q.y; a4 += r.x; a5 += r.y;
        }
        #pragma unroll
        for (int i = 0; i < 3; ++i) {
            const int gro = br + r0 + i;
            if (gro < HH) {
                const int nr = min(gro + RR, HH - 1) - max(gro - RR, 0) + 1;
                const float Nf  = (float)(nr * ncl);
                const float num = fmaf(-(a2 * a3), invS, a1);
                const float den = fabsf(fmaf(-(a2 * a5), invS, a4)) + Nf * 1e-8f;
                const float Av  = __fdividef(num, den);
                const float bv  = __fdividef(fmaf(-Av, a5, a3), a0);
                g_AB[ibase + (size_t)gro * WW + col] = make_float2(Av, bv);
            }
            if (i < 2) {
                const int ha = (r0 + 9 + i) * PH2 + c;
                const int hs = (r0 + i) * PH2 + c;
                const float2 pa = sH0[ha], qa = sH1[ha], ra = sH2[ha];
                const float2 ps = sH0[hs], qs = sH1[hs], rs = sH2[hs];
                a0 += pa.x - ps.x; a1 += pa.y - ps.y;
                a2 += qa.x - qs.x; a3 += qa.y - qs.y;
                a4 += ra.x - rs.x; a5 += ra.y - rs.y;
            }
        }
    }
}

// ---------------- Stage 3: box filter (A,b) + final blend ---------------------
__global__ __launch_bounds__(NTHR) void k_final(
    const float* __restrict__ X, float* __restrict__ out)
{
    __shared__ float2 sAB[HR * PIN2];
    __shared__ float2 sHab[HR * PH2];

    const int tid = threadIdx.x;
    const int img = blockIdx.z;
    const int bc  = blockIdx.x * TC;
    const int br  = blockIdx.y * TR;
    const size_t ibase = (size_t)img * (HH * WW);

    // Phase A: float4 = 2 pixels of (A,b); 640 items
    #pragma unroll
    for (int it = 0; it < 3; ++it) {
        const int idx = tid + it * NTHR;
        if (idx < HR * (HC / 2)) {
            const int rh = idx / (HC / 2);
            const int vq = idx % (HC / 2);        // float4 index in row
            const int gr = br - RR + rh;
            const int gc = bc - RR + vq * 2;      // even pixel col
            float4 v = make_float4(0.f,0.f,0.f,0.f);
            if (gr >= 0 && gr < HH && gc >= 0 && gc < WW) {
                const size_t o = ibase + (size_t)gr * WW + gc;
                v = *(const float4*)(g_AB + o);
            }
            const int sb2 = rh * PIN2 + vq * 2;
            sAB[sb2+0] = make_float2(v.x, v.y);
            sAB[sb2+1] = make_float2(v.z, v.w);
        }
    }
    __syncthreads();

    // Phase B: horizontal 9-tap, sliding over 4 cols per thread
    {
        const int rh = tid & (HR - 1);
        const int cg = tid >> 5;
        const int b2 = rh * PIN2 + cg * 4;
        const int hb = rh * PH2  + cg * 4;
        float hA = 0.f, hB = 0.f;
        #pragma unroll
        for (int d = 0; d < 9; ++d) {
            const float2 ab = sAB[b2 + d];
            hA += ab.x; hB += ab.y;
        }
        sHab[hb] = make_float2(hA, hB);
        #pragma unroll
        for (int s = 1; s < 4; ++s) {
            const float2 aa = sAB[b2 + 8 + s];
            const float2 as = sAB[b2 + s - 1];
            hA += aa.x - as.x;
            hB += aa.y - as.y;
            sHab[hb + s] = make_float2(hA, hB);
        }
    }
    __syncthreads();

    // Phase C: vertical 9-tap sliding + blend
    {
        const int c   = tid & 31;
        const int seg = tid >> 5;
        const int col = bc + c;
        const int ncl = min(col + RR, WW - 1) - max(col - RR, 0) + 1;
        const int r0 = seg * 3;

        float aA = 0.f, aB = 0.f;
        #pragma unroll
        for (int d = 0; d < 9; ++d) {
            const float2 h = sHab[(r0 + d) * PH2 + c];
            aA += h.x; aB += h.y;
        }
        #pragma unroll
        for (int i = 0; i < 3; ++i) {
            const int gro = br + r0 + i;
            if (gro < HH) {
                const int nr = min(gro + RR, HH - 1) - max(gro - RR, 0) + 1;
                const float rcpN = __fdividef(1.f, (float)(nr * ncl));
                const size_t o = ibase + (size_t)gro * WW + col;
                const float xv = X[o];
                out[o] = (aA * xv + aB) * rcpN;
            }
            if (i < 2) {
                const float2 ha = sHab[(r0 + 9 + i) * PH2 + c];
                const float2 hs = sHab[(r0 + i) * PH2 + c];
                aA += ha.x - hs.x;
                aB += ha.y - hs.y;
            }
        }
    }
}

extern "C" void kernel_launch(void* const* d_in, const int* in_sizes, int n_in,
                              void* d_out, int out_size) {
    const float* x = (const float*)d_in[0];  // lr_x
    const float* y = (const float*)d_in[1];  // lr_y
    const float* a = (const float*)d_in[2];  // l_a
    float* out = (float*)d_out;

    k_sum_partial<<<2048, 256>>>(a);
    k_sum_final<<<1, 256>>>();

    dim3 grid(WW / TC, GY, NIMG);  // 16 x 22 x 64
    k_stats<<<grid, NTHR>>>(x, y, a);
    k_final<<<grid, NTHR>>>(x, out);
}